// round 2
// baseline (speedup 1.0000x reference)
#include <cuda_runtime.h>
#include <math.h>

// SO3Reparameterize: z = exp(mu) @ exp(L @ (sqrt(softplus(x@Wd+bd)) * eps))
// Fused triple-GEMV (65536x1024 @ 1024x9) + per-row Rodrigues epilogue.
// Memory-bound design: x read once (256MB), weights broadcast from static smem
// as packed f32x2 pairs, fma.rn.f32x2 mainloop. Static smem < 48KB (no
// cudaFuncSetAttribute needed).

#define D_IN    1024
#define THREADS 128
#define TILE_R  128          // rows per block (1 per thread)
#define KC      16           // k-chunk
#define ROWPAD  20           // floats per xs row (odd multiple of 4 -> conflict-free LDS.128)
#define NCHUNK  (D_IN / KC)  // 64
#define NPAIR   (D_IN / 2)   // 512

typedef unsigned long long u64;

__device__ __forceinline__ u64 pack2(float a, float b) {
    u64 r;
    asm("mov.b64 %0, {%1, %2};" : "=l"(r) : "r"(__float_as_uint(a)), "r"(__float_as_uint(b)));
    return r;
}
__device__ __forceinline__ void unpack2(u64 v, float& a, float& b) {
    unsigned lo, hi;
    asm("mov.b64 {%0, %1}, %2;" : "=r"(lo), "=r"(hi) : "l"(v));
    a = __uint_as_float(lo);
    b = __uint_as_float(hi);
}
__device__ __forceinline__ void ffma2(u64& acc, u64 x, u64 w) {
    asm("fma.rn.f32x2 %0, %1, %2, %0;" : "+l"(acc) : "l"(x), "l"(w));
}

__device__ __forceinline__ void rodrigues(float vx, float vy, float vz, float* R) {
    float th  = sqrtf(vx * vx + vy * vy + vz * vz);
    float inv = 1.0f / th;
    float ux = vx * inv, uy = vy * inv, uz = vz * inv;
    float s = sinf(th), c = cosf(th), C = 1.0f - c;
    R[0] = c + ux * ux * C;      R[1] = ux * uy * C - uz * s;  R[2] = ux * uz * C + uy * s;
    R[3] = uy * ux * C + uz * s; R[4] = c + uy * uy * C;       R[5] = uy * uz * C - ux * s;
    R[6] = uz * ux * C - uy * s; R[7] = uz * uy * C + ux * s;  R[8] = c + uz * uz * C;
}

__device__ __forceinline__ float softplus_stable(float t) {
    return fmaxf(t, 0.0f) + log1pf(expf(-fabsf(t)));
}

__global__ void __launch_bounds__(THREADS)
so3_kernel(const float* __restrict__ x, const float* __restrict__ eps,
           const float* __restrict__ Wmu, const float* __restrict__ bmu,
           const float* __restrict__ Wd,  const float* __restrict__ bd,
           const float* __restrict__ Wl,  const float* __restrict__ bl,
           float* __restrict__ out, int B, int n)
{
    __shared__ float xs[TILE_R * ROWPAD];        // 10,240 B
    __shared__ u64   wpk[NPAIR * 9];             // 36,864 B  (total 47,104 B)

    const int tid  = threadIdx.x;
    const int row0 = blockIdx.x * TILE_R;
    const int row  = row0 + tid;

    // Build packed weight pairs: wpk[k2*9 + j] = (W[2k2][col], W[2k2+1][col]),
    // j: 0-2 = Wmu cols, 3-5 = Wd cols, 6-8 = Wl cols.
    for (int i = tid; i < NPAIR * 9; i += THREADS) {
        int k2 = i / 9, j = i - k2 * 9;
        const float* W;
        int c;
        if (j < 3)      { W = Wmu; c = j; }
        else if (j < 6) { W = Wd;  c = j - 3; }
        else            { W = Wl;  c = j - 6; }
        float lo = W[(2 * k2) * 3 + c];
        float hi = W[(2 * k2 + 1) * 3 + c];
        wpk[i] = pack2(lo, hi);
    }

    u64 acc[9];
#pragma unroll
    for (int j = 0; j < 9; j++) acc[j] = 0ull;

#pragma unroll 1
    for (int ch = 0; ch < NCHUNK; ch++) {
        const int k0 = ch * KC;

        // Stage x tile: TILE_R rows x KC floats.
        // Mapping: 4 consecutive threads cover one row's 64B (full coalescing).
#pragma unroll
        for (int i = 0; i < (TILE_R * KC / 4) / THREADS; i++) {   // 4 float4/thread
            int g  = tid + i * THREADS;
            int rl = g >> 2;
            int cf = g & 3;
            int gr = row0 + rl;
            float4 v = make_float4(0.f, 0.f, 0.f, 0.f);
            if (gr < B)
                v = *(const float4*)&x[(size_t)gr * D_IN + k0 + cf * 4];
            *(float4*)&xs[rl * ROWPAD + cf * 4] = v;
        }
        __syncthreads();

        const float4* xa  = (const float4*)&xs[tid * ROWPAD];
        const int     kpb = k0 >> 1;

#pragma unroll
        for (int p = 0; p < KC / 4; p++) {        // 4
            float4 A = xa[p];
            u64 a01 = pack2(A.x, A.y), a23 = pack2(A.z, A.w);
            const u64* w0 = &wpk[(kpb + 2 * p) * 9];  // pair (k0+4p,   k0+4p+1)
            const u64* w1 = w0 + 9;                   // pair (k0+4p+2, k0+4p+3)
#pragma unroll
            for (int j = 0; j < 9; j++) {
                u64 wj0 = w0[j];                      // broadcast LDS.64, conflict-free
                u64 wj1 = w1[j];
                ffma2(acc[j], a01, wj0);
                ffma2(acc[j], a23, wj1);
            }
        }
        __syncthreads();
    }

    if (row >= B) return;

    // --- Epilogue: biases, softplus, Cholesky-ish L, double Rodrigues, 3x3 matmul ---
    float s[9];
#pragma unroll
    for (int j = 0; j < 9; j++) {
        float lo, hi;
        unpack2(acc[j], lo, hi);
        s[j] = lo + hi;
    }
    float m0 = s[0] + bmu[0], m1 = s[1] + bmu[1], m2 = s[2] + bmu[2];
    float sd0 = sqrtf(softplus_stable(s[3] + bd[0]));
    float sd1 = sqrtf(softplus_stable(s[4] + bd[1]));
    float sd2 = sqrtf(softplus_stable(s[5] + bd[2]));
    float l0 = s[6] + bl[0], l1 = s[7] + bl[1], l2 = s[8] + bl[2];

    float Rm[9];
    rodrigues(m0, m1, m2, Rm);

    for (int jn = 0; jn < n; jn++) {
        size_t base = (size_t)(jn * B + row) * 3;
        float e0 = eps[base + 0], e1 = eps[base + 1], e2 = eps[base + 2];
        float a0 = sd0 * e0, a1 = sd1 * e1, a2 = sd2 * e2;
        float v0 = a0;
        float v1 = l0 * a0 + a1;
        float v2 = l1 * a0 + l2 * a1 + a2;

        float Rv[9];
        rodrigues(v0, v1, v2, Rv);

        float* o = out + (size_t)(jn * B + row) * 9;
#pragma unroll
        for (int i = 0; i < 3; i++) {
#pragma unroll
            for (int k = 0; k < 3; k++) {
                o[i * 3 + k] = Rm[i * 3 + 0] * Rv[0 * 3 + k]
                             + Rm[i * 3 + 1] * Rv[1 * 3 + k]
                             + Rm[i * 3 + 2] * Rv[2 * 3 + k];
            }
        }
    }
}

extern "C" void kernel_launch(void* const* d_in, const int* in_sizes, int n_in,
                              void* d_out, int out_size)
{
    const float* x   = (const float*)d_in[0];
    const float* eps = (const float*)d_in[1];
    const float* Wmu = (const float*)d_in[2];
    const float* bmu = (const float*)d_in[3];
    const float* Wd  = (const float*)d_in[4];
    const float* bd  = (const float*)d_in[5];
    const float* Wl  = (const float*)d_in[6];
    const float* bl  = (const float*)d_in[7];

    const int B = in_sizes[0] / D_IN;
    const int n = in_sizes[1] / (B * 3);

    const int grid = (B + TILE_R - 1) / TILE_R;
    so3_kernel<<<grid, THREADS>>>(x, eps, Wmu, bmu, Wd, bd, Wl, bl,
                                  (float*)d_out, B, n);
}

// round 3
// speedup vs baseline: 1.0290x; 1.0290x over previous
#include <cuda_runtime.h>
#include <math.h>

// SO3Reparameterize: fused triple-GEMV (65536x1024 @ 1024x9) + Rodrigues epilogue.
// R3: 2 rows/thread, transposed weight layout [j][kpair] read as broadcast
// LDS.128 (ulonglong2), x read from smem as ulonglong2 (no pack MOVs),
// register-prefetch of next x chunk to hide DRAM latency.

#define D_IN    1024
#define THREADS 64
#define TILE_R  128          // rows per block (2 per thread)
#define KC      16           // k-chunk
#define ROWPAD  20           // floats per xs row (conflict-free LDS.128 phases)
#define NCHUNK  (D_IN / KC)  // 64
#define NPAIR   (D_IN / 2)   // 512

typedef unsigned long long u64;

__device__ __forceinline__ u64 pack2(float a, float b) {
    u64 r;
    asm("mov.b64 %0, {%1, %2};" : "=l"(r) : "r"(__float_as_uint(a)), "r"(__float_as_uint(b)));
    return r;
}
__device__ __forceinline__ void unpack2(u64 v, float& a, float& b) {
    unsigned lo, hi;
    asm("mov.b64 {%0, %1}, %2;" : "=r"(lo), "=r"(hi) : "l"(v));
    a = __uint_as_float(lo);
    b = __uint_as_float(hi);
}
__device__ __forceinline__ void ffma2(u64& acc, u64 x, u64 w) {
    asm("fma.rn.f32x2 %0, %1, %2, %0;" : "+l"(acc) : "l"(x), "l"(w));
}

__device__ __forceinline__ void rodrigues(float vx, float vy, float vz, float* R) {
    float th  = sqrtf(vx * vx + vy * vy + vz * vz);
    float inv = 1.0f / th;
    float ux = vx * inv, uy = vy * inv, uz = vz * inv;
    float s = sinf(th), c = cosf(th), C = 1.0f - c;
    R[0] = c + ux * ux * C;      R[1] = ux * uy * C - uz * s;  R[2] = ux * uz * C + uy * s;
    R[3] = uy * ux * C + uz * s; R[4] = c + uy * uy * C;       R[5] = uy * uz * C - ux * s;
    R[6] = uz * ux * C - uy * s; R[7] = uz * uy * C + ux * s;  R[8] = c + uz * uz * C;
}

__device__ __forceinline__ float softplus_stable(float t) {
    return fmaxf(t, 0.0f) + log1pf(expf(-fabsf(t)));
}

__device__ __forceinline__ void epilogue_row(
    int row, int B, int n, const u64* acc,
    const float* __restrict__ bmu, const float* __restrict__ bd,
    const float* __restrict__ bl,
    const float* __restrict__ eps, float* __restrict__ out)
{
    float s[9];
#pragma unroll
    for (int j = 0; j < 9; j++) {
        float lo, hi;
        unpack2(acc[j], lo, hi);
        s[j] = lo + hi;
    }
    float m0 = s[0] + bmu[0], m1 = s[1] + bmu[1], m2 = s[2] + bmu[2];
    float sd0 = sqrtf(softplus_stable(s[3] + bd[0]));
    float sd1 = sqrtf(softplus_stable(s[4] + bd[1]));
    float sd2 = sqrtf(softplus_stable(s[5] + bd[2]));
    float l0 = s[6] + bl[0], l1 = s[7] + bl[1], l2 = s[8] + bl[2];

    float Rm[9];
    rodrigues(m0, m1, m2, Rm);

    for (int jn = 0; jn < n; jn++) {
        size_t base = (size_t)(jn * B + row) * 3;
        float e0 = eps[base + 0], e1 = eps[base + 1], e2 = eps[base + 2];
        float a0 = sd0 * e0, a1 = sd1 * e1, a2 = sd2 * e2;
        float v0 = a0;
        float v1 = l0 * a0 + a1;
        float v2 = l1 * a0 + l2 * a1 + a2;

        float Rv[9];
        rodrigues(v0, v1, v2, Rv);

        float* o = out + (size_t)(jn * B + row) * 9;
#pragma unroll
        for (int i = 0; i < 3; i++) {
#pragma unroll
            for (int k = 0; k < 3; k++) {
                o[i * 3 + k] = Rm[i * 3 + 0] * Rv[0 * 3 + k]
                             + Rm[i * 3 + 1] * Rv[1 * 3 + k]
                             + Rm[i * 3 + 2] * Rv[2 * 3 + k];
            }
        }
    }
}

__global__ void __launch_bounds__(THREADS, 8)
so3_kernel(const float* __restrict__ x, const float* __restrict__ eps,
           const float* __restrict__ Wmu, const float* __restrict__ bmu,
           const float* __restrict__ Wd,  const float* __restrict__ bd,
           const float* __restrict__ Wl,  const float* __restrict__ bl,
           float* __restrict__ out, int B, int n)
{
    __shared__ u64   wpkT[9 * NPAIR];            // 36,864 B  [j][k2] transposed
    __shared__ float xs[TILE_R * ROWPAD];        // 10,240 B  (total 47,104 B)

    const int tid  = threadIdx.x;
    const int row0 = blockIdx.x * TILE_R;
    const int ra   = row0 + tid;
    const int rb   = row0 + tid + THREADS;

    // Stage weights transposed: wpkT[j*NPAIR + k2] = (W[2k2][c], W[2k2+1][c]).
    // j: 0-2 = Wmu cols, 3-5 = Wd cols, 6-8 = Wl cols.
    for (int i = tid; i < 9 * NPAIR; i += THREADS) {
        int j = i / NPAIR, k2 = i - j * NPAIR;
        const float* W;
        int c;
        if (j < 3)      { W = Wmu; c = j; }
        else if (j < 6) { W = Wd;  c = j - 3; }
        else            { W = Wl;  c = j - 6; }
        wpkT[i] = pack2(W[(2 * k2) * 3 + c], W[(2 * k2 + 1) * 3 + c]);
    }

    u64 accA[9], accB[9];
#pragma unroll
    for (int j = 0; j < 9; j++) { accA[j] = 0ull; accB[j] = 0ull; }

    // Each chunk: TILE_R*KC floats = 512 float4, 8 per thread.
    // Mapping: 4 consecutive threads cover one row's 64B.
    float4 pf[8];

    // Prologue: load chunk 0 into regs, store to smem.
#pragma unroll
    for (int i = 0; i < 8; i++) {
        int g  = tid + i * THREADS;
        int rl = g >> 2, cf = g & 3;
        pf[i] = *(const float4*)&x[(size_t)(row0 + rl) * D_IN + cf * 4];
    }
#pragma unroll
    for (int i = 0; i < 8; i++) {
        int g  = tid + i * THREADS;
        int rl = g >> 2, cf = g & 3;
        *(float4*)&xs[rl * ROWPAD + cf * 4] = pf[i];
    }
    __syncthreads();

#pragma unroll 1
    for (int ch = 0; ch < NCHUNK; ch++) {
        // Prefetch next chunk into registers (LDG in flight during compute).
        if (ch + 1 < NCHUNK) {
            const int k0n = (ch + 1) * KC;
#pragma unroll
            for (int i = 0; i < 8; i++) {
                int g  = tid + i * THREADS;
                int rl = g >> 2, cf = g & 3;
                pf[i] = *(const float4*)&x[(size_t)(row0 + rl) * D_IN + k0n + cf * 4];
            }
        }

        // Compute current chunk from smem.
        const int pbase = ch * (KC / 2);   // k-pair index of chunk start
#pragma unroll
        for (int p = 0; p < KC / 4; p++) {                  // 4 quads
            ulonglong2 xa = *(const ulonglong2*)&xs[tid * ROWPAD + p * 4];
            ulonglong2 xb = *(const ulonglong2*)&xs[(tid + THREADS) * ROWPAD + p * 4];
#pragma unroll
            for (int j = 0; j < 9; j++) {
                // broadcast LDS.128: two k-pairs of output column j
                ulonglong2 w = *(const ulonglong2*)&wpkT[j * NPAIR + pbase + 2 * p];
                ffma2(accA[j], xa.x, w.x);
                ffma2(accB[j], xb.x, w.x);
                ffma2(accA[j], xa.y, w.y);
                ffma2(accB[j], xb.y, w.y);
            }
        }
        __syncthreads();

        // Commit prefetched chunk to smem.
        if (ch + 1 < NCHUNK) {
#pragma unroll
            for (int i = 0; i < 8; i++) {
                int g  = tid + i * THREADS;
                int rl = g >> 2, cf = g & 3;
                *(float4*)&xs[rl * ROWPAD + cf * 4] = pf[i];
            }
        }
        __syncthreads();
    }

    if (ra < B) epilogue_row(ra, B, n, accA, bmu, bd, bl, eps, out);
    if (rb < B) epilogue_row(rb, B, n, accB, bmu, bd, bl, eps, out);
}

extern "C" void kernel_launch(void* const* d_in, const int* in_sizes, int n_in,
                              void* d_out, int out_size)
{
    const float* x   = (const float*)d_in[0];
    const float* eps = (const float*)d_in[1];
    const float* Wmu = (const float*)d_in[2];
    const float* bmu = (const float*)d_in[3];
    const float* Wd  = (const float*)d_in[4];
    const float* bd  = (const float*)d_in[5];
    const float* Wl  = (const float*)d_in[6];
    const float* bl  = (const float*)d_in[7];

    const int B = in_sizes[0] / D_IN;
    const int n = in_sizes[1] / (B * 3);

    const int grid = (B + TILE_R - 1) / TILE_R;
    so3_kernel<<<grid, THREADS>>>(x, eps, Wmu, bmu, Wd, bd, Wl, bl,
                                  (float*)d_out, B, n);
}

// round 4
// speedup vs baseline: 1.1874x; 1.1539x over previous
#include <cuda_runtime.h>
#include <math.h>

// SO3Reparameterize: fused triple-GEMV (65536x1024 @ 1024x9) + Rodrigues epilogue.
// R4: cp.async 5-stage ring buffer (structural DRAM latency hiding), 1 row/thread,
// transposed weight layout [j][kpair] read as broadcast LDS.128, fma.rn.f32x2.

#define D_IN    1024
#define THREADS 128
#define TILE_R  128          // rows per block (1 per thread)
#define KC      16           // k-chunk
#define ROWPAD  20           // floats per xs row (conflict-free LDS.128 phases)
#define NCHUNK  (D_IN / KC)  // 64
#define NPAIR   (D_IN / 2)   // 512
#define STAGES  5
#define XS_FLOATS (TILE_R * ROWPAD)               // 2560 floats / stage
#define SMEM_BYTES (9 * NPAIR * 8 + STAGES * XS_FLOATS * 4)   // 36864 + 51200 = 88064

typedef unsigned long long u64;

__device__ __forceinline__ u64 pack2(float a, float b) {
    u64 r;
    asm("mov.b64 %0, {%1, %2};" : "=l"(r) : "r"(__float_as_uint(a)), "r"(__float_as_uint(b)));
    return r;
}
__device__ __forceinline__ void unpack2(u64 v, float& a, float& b) {
    unsigned lo, hi;
    asm("mov.b64 {%0, %1}, %2;" : "=r"(lo), "=r"(hi) : "l"(v));
    a = __uint_as_float(lo);
    b = __uint_as_float(hi);
}
__device__ __forceinline__ void ffma2(u64& acc, u64 x, u64 w) {
    asm("fma.rn.f32x2 %0, %1, %2, %0;" : "+l"(acc) : "l"(x), "l"(w));
}
__device__ __forceinline__ void cp_async16(unsigned saddr, const void* gptr) {
    asm volatile("cp.async.cg.shared.global [%0], [%1], 16;" :: "r"(saddr), "l"(gptr));
}
__device__ __forceinline__ void cp_commit() {
    asm volatile("cp.async.commit_group;");
}
__device__ __forceinline__ void cp_wait3() {
    asm volatile("cp.async.wait_group 3;");
}

__device__ __forceinline__ void rodrigues(float vx, float vy, float vz, float* R) {
    float th  = sqrtf(vx * vx + vy * vy + vz * vz);
    float inv = 1.0f / th;
    float ux = vx * inv, uy = vy * inv, uz = vz * inv;
    float s = sinf(th), c = cosf(th), C = 1.0f - c;
    R[0] = c + ux * ux * C;      R[1] = ux * uy * C - uz * s;  R[2] = ux * uz * C + uy * s;
    R[3] = uy * ux * C + uz * s; R[4] = c + uy * uy * C;       R[5] = uy * uz * C - ux * s;
    R[6] = uz * ux * C - uy * s; R[7] = uz * uy * C + ux * s;  R[8] = c + uz * uz * C;
}

__device__ __forceinline__ float softplus_stable(float t) {
    return fmaxf(t, 0.0f) + log1pf(expf(-fabsf(t)));
}

__global__ void __launch_bounds__(THREADS)
so3_kernel(const float* __restrict__ x, const float* __restrict__ eps,
           const float* __restrict__ Wmu, const float* __restrict__ bmu,
           const float* __restrict__ Wd,  const float* __restrict__ bd,
           const float* __restrict__ Wl,  const float* __restrict__ bl,
           float* __restrict__ out, int B, int n)
{
    extern __shared__ unsigned char smem_raw[];
    u64*   wpkT = (u64*)smem_raw;                         // [j][k2], 9*512 pairs
    float* xs   = (float*)(smem_raw + 9 * NPAIR * 8);     // [STAGES][TILE_R*ROWPAD]

    const int tid  = threadIdx.x;
    const int row0 = blockIdx.x * TILE_R;
    const int row  = row0 + tid;

    // Staging address components (4 consecutive threads cover one row's 64B).
    const int rl0 = tid >> 2;            // row for i=0 (rows advance by 32 per i)
    const int cf  = tid & 3;             // 16B quarter within the 64B
    const unsigned s_off = (unsigned)((rl0 * ROWPAD + cf * 4) * 4);
    const float* gbase = x + (size_t)(row0 + rl0) * D_IN + cf * 4;

    unsigned xs_base;
    {
        unsigned long long gen = __cvta_generic_to_shared(xs);
        xs_base = (unsigned)gen;
    }

    // Stage weights transposed: wpkT[j*NPAIR + k2] = (W[2k2][c], W[2k2+1][c]).
    for (int i = tid; i < 9 * NPAIR; i += THREADS) {
        int j = i / NPAIR, k2 = i - j * NPAIR;
        const float* W;
        int c;
        if (j < 3)      { W = Wmu; c = j; }
        else if (j < 6) { W = Wd;  c = j - 3; }
        else            { W = Wl;  c = j - 6; }
        wpkT[i] = pack2(W[(2 * k2) * 3 + c], W[(2 * k2 + 1) * 3 + c]);
    }

    // Prologue: issue chunks 0..STAGES-2 into slots 0..STAGES-2.
#pragma unroll
    for (int s = 0; s < STAGES - 1; s++) {
        unsigned slot_base = xs_base + (unsigned)(s * XS_FLOATS * 4);
        const float* g = gbase + s * KC;
#pragma unroll
        for (int i = 0; i < 4; i++)   // rows rl0, rl0+32, rl0+64, rl0+96
            cp_async16(slot_base + s_off + (unsigned)(i * 32 * ROWPAD * 4),
                       g + (size_t)(i * 32) * D_IN);
        cp_commit();
    }

    u64 acc[9];
#pragma unroll
    for (int j = 0; j < 9; j++) acc[j] = 0ull;

    int slot = 0;                 // slot holding chunk ch
    int pslot = STAGES - 1;       // slot to prefetch into

#pragma unroll 1
    for (int ch = 0; ch < NCHUNK; ch++) {
        cp_wait3();               // chunk ch landed (<=3 groups still in flight)
        __syncthreads();          // visible to all threads; fences prior compute

        // Prefetch chunk ch+STAGES-1 into pslot (freed slot of chunk ch-1).
        if (ch + STAGES - 1 < NCHUNK) {
            unsigned slot_base = xs_base + (unsigned)(pslot * XS_FLOATS * 4);
            const float* g = gbase + (ch + STAGES - 1) * KC;
#pragma unroll
            for (int i = 0; i < 4; i++)
                cp_async16(slot_base + s_off + (unsigned)(i * 32 * ROWPAD * 4),
                           g + (size_t)(i * 32) * D_IN);
            cp_commit();
        }

        // Compute chunk ch from smem.
        const float* xrow = xs + slot * XS_FLOATS + tid * ROWPAD;
        const u64*   wch  = wpkT + ch * (KC / 2);
#pragma unroll
        for (int p = 0; p < KC / 4; p++) {                 // 4 quads
            ulonglong2 xa = *(const ulonglong2*)&xrow[p * 4];
#pragma unroll
            for (int j = 0; j < 9; j++) {
                ulonglong2 w = *(const ulonglong2*)&wch[j * NPAIR + 2 * p];  // broadcast
                ffma2(acc[j], xa.x, w.x);
                ffma2(acc[j], xa.y, w.y);
            }
        }

        slot  = (slot  + 1 == STAGES) ? 0 : slot  + 1;
        pslot = (pslot + 1 == STAGES) ? 0 : pslot + 1;
    }

    if (row >= B) return;

    // --- Epilogue ---
    float s[9];
#pragma unroll
    for (int j = 0; j < 9; j++) {
        float lo, hi;
        unpack2(acc[j], lo, hi);
        s[j] = lo + hi;
    }
    float m0 = s[0] + bmu[0], m1 = s[1] + bmu[1], m2 = s[2] + bmu[2];
    float sd0 = sqrtf(softplus_stable(s[3] + bd[0]));
    float sd1 = sqrtf(softplus_stable(s[4] + bd[1]));
    float sd2 = sqrtf(softplus_stable(s[5] + bd[2]));
    float l0 = s[6] + bl[0], l1 = s[7] + bl[1], l2 = s[8] + bl[2];

    float Rm[9];
    rodrigues(m0, m1, m2, Rm);

    for (int jn = 0; jn < n; jn++) {
        size_t base = (size_t)(jn * B + row) * 3;
        float e0 = eps[base + 0], e1 = eps[base + 1], e2 = eps[base + 2];
        float a0 = sd0 * e0, a1 = sd1 * e1, a2 = sd2 * e2;
        float v0 = a0;
        float v1 = l0 * a0 + a1;
        float v2 = l1 * a0 + l2 * a1 + a2;

        float Rv[9];
        rodrigues(v0, v1, v2, Rv);

        float* o = out + (size_t)(jn * B + row) * 9;
#pragma unroll
        for (int i = 0; i < 3; i++) {
#pragma unroll
            for (int k = 0; k < 3; k++) {
                o[i * 3 + k] = Rm[i * 3 + 0] * Rv[0 * 3 + k]
                             + Rm[i * 3 + 1] * Rv[1 * 3 + k]
                             + Rm[i * 3 + 2] * Rv[2 * 3 + k];
            }
        }
    }
}

extern "C" void kernel_launch(void* const* d_in, const int* in_sizes, int n_in,
                              void* d_out, int out_size)
{
    const float* x   = (const float*)d_in[0];
    const float* eps = (const float*)d_in[1];
    const float* Wmu = (const float*)d_in[2];
    const float* bmu = (const float*)d_in[3];
    const float* Wd  = (const float*)d_in[4];
    const float* bd  = (const float*)d_in[5];
    const float* Wl  = (const float*)d_in[6];
    const float* bl  = (const float*)d_in[7];

    const int B = in_sizes[0] / D_IN;
    const int n = in_sizes[1] / (B * 3);

    cudaFuncSetAttribute(so3_kernel, cudaFuncAttributeMaxDynamicSharedMemorySize, SMEM_BYTES);

    const int grid = (B + TILE_R - 1) / TILE_R;
    so3_kernel<<<grid, THREADS, SMEM_BYTES>>>(x, eps, Wmu, bmu, Wd, bd, Wl, bl,
                                              (float*)d_out, B, n);
}

// round 6
// speedup vs baseline: 1.5410x; 1.2977x over previous
#include <cuda_runtime.h>
#include <math.h>

// SO3Reparameterize: fused triple-GEMV (65536x1024 @ 1024x9) + Rodrigues epilogue.
// R6: 2 rows/thread (halves weight-broadcast smem-port cost per row),
// cp.async 3-stage ring, transposed weights [j][kpair] via broadcast LDS.128,
// fma.rn.f32x2 mainloop.

#define D_IN    1024
#define THREADS 128
#define TILE_R  256          // rows per block (2 per thread: tid, tid+128)
#define KC      16           // k-chunk
#define ROWPAD  20           // floats per xs row (conflict-free LDS.128 phases)
#define NCHUNK  (D_IN / KC)  // 64
#define NPAIR   (D_IN / 2)   // 512
#define STAGES  3
#define XS_FLOATS (TILE_R * ROWPAD)                           // 5120 floats/stage
#define SMEM_BYTES (9 * NPAIR * 8 + STAGES * XS_FLOATS * 4)   // 36864 + 61440 = 98304

typedef unsigned long long u64;

__device__ __forceinline__ u64 pack2(float a, float b) {
    u64 r;
    asm("mov.b64 %0, {%1, %2};" : "=l"(r) : "r"(__float_as_uint(a)), "r"(__float_as_uint(b)));
    return r;
}
__device__ __forceinline__ void unpack2(u64 v, float& a, float& b) {
    unsigned lo, hi;
    asm("mov.b64 {%0, %1}, %2;" : "=r"(lo), "=r"(hi) : "l"(v));
    a = __uint_as_float(lo);
    b = __uint_as_float(hi);
}
__device__ __forceinline__ void ffma2(u64& acc, u64 x, u64 w) {
    asm("fma.rn.f32x2 %0, %1, %2, %0;" : "+l"(acc) : "l"(x), "l"(w));
}
__device__ __forceinline__ void cp_async16(unsigned saddr, const void* gptr) {
    asm volatile("cp.async.cg.shared.global [%0], [%1], 16;" :: "r"(saddr), "l"(gptr));
}
__device__ __forceinline__ void cp_commit() {
    asm volatile("cp.async.commit_group;");
}
__device__ __forceinline__ void cp_wait1() {
    asm volatile("cp.async.wait_group 1;");
}

__device__ __forceinline__ void rodrigues(float vx, float vy, float vz, float* R) {
    float th  = sqrtf(vx * vx + vy * vy + vz * vz);
    float inv = 1.0f / th;
    float ux = vx * inv, uy = vy * inv, uz = vz * inv;
    float s = sinf(th), c = cosf(th), C = 1.0f - c;
    R[0] = c + ux * ux * C;      R[1] = ux * uy * C - uz * s;  R[2] = ux * uz * C + uy * s;
    R[3] = uy * ux * C + uz * s; R[4] = c + uy * uy * C;       R[5] = uy * uz * C - ux * s;
    R[6] = uz * ux * C - uy * s; R[7] = uz * uy * C + ux * s;  R[8] = c + uz * uz * C;
}

__device__ __forceinline__ float softplus_stable(float t) {
    return fmaxf(t, 0.0f) + log1pf(expf(-fabsf(t)));
}

__device__ __forceinline__ void epilogue_row(
    int row, int B, int n, const u64* acc,
    const float* __restrict__ bmu, const float* __restrict__ bd,
    const float* __restrict__ bl,
    const float* __restrict__ eps, float* __restrict__ out)
{
    float s[9];
#pragma unroll
    for (int j = 0; j < 9; j++) {
        float lo, hi;
        unpack2(acc[j], lo, hi);
        s[j] = lo + hi;
    }
    float m0 = s[0] + bmu[0], m1 = s[1] + bmu[1], m2 = s[2] + bmu[2];
    float sd0 = sqrtf(softplus_stable(s[3] + bd[0]));
    float sd1 = sqrtf(softplus_stable(s[4] + bd[1]));
    float sd2 = sqrtf(softplus_stable(s[5] + bd[2]));
    float l0 = s[6] + bl[0], l1 = s[7] + bl[1], l2 = s[8] + bl[2];

    float Rm[9];
    rodrigues(m0, m1, m2, Rm);

    for (int jn = 0; jn < n; jn++) {
        size_t base = (size_t)(jn * B + row) * 3;
        float e0 = eps[base + 0], e1 = eps[base + 1], e2 = eps[base + 2];
        float a0 = sd0 * e0, a1 = sd1 * e1, a2 = sd2 * e2;
        float v0 = a0;
        float v1 = l0 * a0 + a1;
        float v2 = l1 * a0 + l2 * a1 + a2;

        float Rv[9];
        rodrigues(v0, v1, v2, Rv);

        float* o = out + (size_t)(jn * B + row) * 9;
#pragma unroll
        for (int i = 0; i < 3; i++) {
#pragma unroll
            for (int k = 0; k < 3; k++) {
                o[i * 3 + k] = Rm[i * 3 + 0] * Rv[0 * 3 + k]
                             + Rm[i * 3 + 1] * Rv[1 * 3 + k]
                             + Rm[i * 3 + 2] * Rv[2 * 3 + k];
            }
        }
    }
}

__global__ void __launch_bounds__(THREADS)
so3_kernel(const float* __restrict__ x, const float* __restrict__ eps,
           const float* __restrict__ Wmu, const float* __restrict__ bmu,
           const float* __restrict__ Wd,  const float* __restrict__ bd,
           const float* __restrict__ Wl,  const float* __restrict__ bl,
           float* __restrict__ out, int B, int n)
{
    extern __shared__ unsigned char smem_raw[];
    u64*   wpkT = (u64*)smem_raw;                         // [j][k2], 9*512 pairs
    float* xs   = (float*)(smem_raw + 9 * NPAIR * 8);     // [STAGES][XS_FLOATS]

    const int tid  = threadIdx.x;
    const int row0 = blockIdx.x * TILE_R;
    const int ra   = row0 + tid;
    const int rb   = row0 + tid + THREADS;

    // Staging: per chunk, TILE_R*KC floats = 1024 float4, 8 per thread.
    // 4 consecutive threads cover one row's 64B; rows advance 32 per i.
    const int rl0 = tid >> 2;
    const int cf  = tid & 3;
    const unsigned s_off = (unsigned)((rl0 * ROWPAD + cf * 4) * 4);
    int grow = row0 + rl0; if (grow >= B) grow = B - 1;    // clamp (safety)
    const float* gbase = x + (size_t)grow * D_IN + cf * 4;

    unsigned xs_base = (unsigned)__cvta_generic_to_shared(xs);

    // Stage weights transposed: wpkT[j*NPAIR + k2] = (W[2k2][c], W[2k2+1][c]).
    for (int i = tid; i < 9 * NPAIR; i += THREADS) {
        int j = i / NPAIR, k2 = i - j * NPAIR;
        const float* W;
        int c;
        if (j < 3)      { W = Wmu; c = j; }
        else if (j < 6) { W = Wd;  c = j - 3; }
        else            { W = Wl;  c = j - 6; }
        wpkT[i] = pack2(W[(2 * k2) * 3 + c], W[(2 * k2 + 1) * 3 + c]);
    }

    // Prologue: issue chunks 0..STAGES-2 into slots 0..STAGES-2.
#pragma unroll
    for (int s = 0; s < STAGES - 1; s++) {
        unsigned slot_base = xs_base + (unsigned)(s * XS_FLOATS * 4);
        const float* g = gbase + s * KC;
#pragma unroll
        for (int i = 0; i < 8; i++)   // rows rl0 + 32*i
            cp_async16(slot_base + s_off + (unsigned)(i * 32 * ROWPAD * 4),
                       g + (size_t)(i * 32) * D_IN);
        cp_commit();
    }

    u64 accA[9], accB[9];
#pragma unroll
    for (int j = 0; j < 9; j++) { accA[j] = 0ull; accB[j] = 0ull; }

    int slot  = 0;                // slot holding chunk ch
    int pslot = STAGES - 1;       // slot to prefetch into (== slot of ch-1)

#pragma unroll 1
    for (int ch = 0; ch < NCHUNK; ch++) {
        cp_wait1();               // chunk ch landed (<=1 group still in flight)
        __syncthreads();          // all warps done with chunk ch-1 -> its slot reusable

        if (ch + STAGES - 1 < NCHUNK) {
            unsigned slot_base = xs_base + (unsigned)(pslot * XS_FLOATS * 4);
            const float* g = gbase + (ch + STAGES - 1) * KC;
#pragma unroll
            for (int i = 0; i < 8; i++)
                cp_async16(slot_base + s_off + (unsigned)(i * 32 * ROWPAD * 4),
                           g + (size_t)(i * 32) * D_IN);
            cp_commit();
        }

        // Compute chunk ch for both rows from smem.
        const float* xra = xs + slot * XS_FLOATS + tid * ROWPAD;
        const float* xrb = xra + THREADS * ROWPAD;
        const u64*   wch = wpkT + ch * (KC / 2);
#pragma unroll
        for (int p = 0; p < KC / 4; p++) {                 // 4 quads
            ulonglong2 xa = *(const ulonglong2*)&xra[p * 4];
            ulonglong2 xb = *(const ulonglong2*)&xrb[p * 4];
#pragma unroll
            for (int j = 0; j < 9; j++) {
                ulonglong2 w = *(const ulonglong2*)&wch[j * NPAIR + 2 * p];  // broadcast
                ffma2(accA[j], xa.x, w.x);
                ffma2(accB[j], xb.x, w.x);
                ffma2(accA[j], xa.y, w.y);
                ffma2(accB[j], xb.y, w.y);
            }
        }

        slot  = (slot  + 1 == STAGES) ? 0 : slot  + 1;
        pslot = (pslot + 1 == STAGES) ? 0 : pslot + 1;
    }

    if (ra < B) epilogue_row(ra, B, n, accA, bmu, bd, bl, eps, out);
    if (rb < B) epilogue_row(rb, B, n, accB, bmu, bd, bl, eps, out);
}

extern "C" void kernel_launch(void* const* d_in, const int* in_sizes, int n_in,
                              void* d_out, int out_size)
{
    const float* x   = (const float*)d_in[0];
    const float* eps = (const float*)d_in[1];
    const float* Wmu = (const float*)d_in[2];
    const float* bmu = (const float*)d_in[3];
    const float* Wd  = (const float*)d_in[4];
    const float* bd  = (const float*)d_in[5];
    const float* Wl  = (const float*)d_in[6];
    const float* bl  = (const float*)d_in[7];

    const int B = in_sizes[0] / D_IN;
    const int n = in_sizes[1] / (B * 3);

    cudaFuncSetAttribute(so3_kernel, cudaFuncAttributeMaxDynamicSharedMemorySize, SMEM_BYTES);

    const int grid = (B + TILE_R - 1) / TILE_R;
    so3_kernel<<<grid, THREADS, SMEM_BYTES>>>(x, eps, Wmu, bmu, Wd, bd, Wl, bl,
                                              (float*)d_out, B, n);
}

// round 7
// speedup vs baseline: 1.7586x; 1.1412x over previous
#include <cuda_runtime.h>
#include <math.h>

// SO3Reparameterize: fused triple-GEMV (65536x1024 @ 1024x9) + Rodrigues epilogue.
// R7: warp-autonomous cp.async pipelines. Each warp stages its own 64 rows into
// a private smem partition and runs a private 3-stage ring (per-warp
// wait_group + syncwarp, NO __syncthreads in the mainloop). 2 rows/thread,
// transposed weights [j][kpair] via broadcast LDS.128, fma.rn.f32x2.

#define D_IN    1024
#define THREADS 128
#define TILE_R  256          // rows per block (2 per thread)
#define KC      16           // k-chunk
#define ROWPAD  20           // floats per staged row
#define NCHUNK  (D_IN / KC)  // 64
#define NPAIR   (D_IN / 2)   // 512
#define STAGES  3
#define WROWS   64                                   // rows per warp
#define WARP_FLOATS (WROWS * ROWPAD)                 // 1280 floats = 5120 B
#define XS_FLOATS   (4 * WARP_FLOATS)                // per stage, 4 warps = 20480 B
#define SMEM_BYTES  (9 * NPAIR * 8 + STAGES * XS_FLOATS * 4)   // 36864+61440=98304

typedef unsigned long long u64;

__device__ __forceinline__ u64 pack2(float a, float b) {
    u64 r;
    asm("mov.b64 %0, {%1, %2};" : "=l"(r) : "r"(__float_as_uint(a)), "r"(__float_as_uint(b)));
    return r;
}
__device__ __forceinline__ void unpack2(u64 v, float& a, float& b) {
    unsigned lo, hi;
    asm("mov.b64 {%0, %1}, %2;" : "=r"(lo), "=r"(hi) : "l"(v));
    a = __uint_as_float(lo);
    b = __uint_as_float(hi);
}
__device__ __forceinline__ void ffma2(u64& acc, u64 x, u64 w) {
    asm("fma.rn.f32x2 %0, %1, %2, %0;" : "+l"(acc) : "l"(x), "l"(w));
}
__device__ __forceinline__ void cp_async16(unsigned saddr, const void* gptr) {
    asm volatile("cp.async.cg.shared.global [%0], [%1], 16;" :: "r"(saddr), "l"(gptr));
}
__device__ __forceinline__ void cp_commit() {
    asm volatile("cp.async.commit_group;");
}
__device__ __forceinline__ void cp_wait1() {
    asm volatile("cp.async.wait_group 1;");
}

__device__ __forceinline__ void rodrigues(float vx, float vy, float vz, float* R) {
    float th  = sqrtf(vx * vx + vy * vy + vz * vz);
    float inv = 1.0f / th;
    float ux = vx * inv, uy = vy * inv, uz = vz * inv;
    float s = sinf(th), c = cosf(th), C = 1.0f - c;
    R[0] = c + ux * ux * C;      R[1] = ux * uy * C - uz * s;  R[2] = ux * uz * C + uy * s;
    R[3] = uy * ux * C + uz * s; R[4] = c + uy * uy * C;       R[5] = uy * uz * C - ux * s;
    R[6] = uz * ux * C - uy * s; R[7] = uz * uy * C + ux * s;  R[8] = c + uz * uz * C;
}

__device__ __forceinline__ float softplus_stable(float t) {
    return fmaxf(t, 0.0f) + log1pf(expf(-fabsf(t)));
}

__device__ __forceinline__ void epilogue_row(
    int row, int B, int n, const u64* acc,
    const float* __restrict__ bmu, const float* __restrict__ bd,
    const float* __restrict__ bl,
    const float* __restrict__ eps, float* __restrict__ out)
{
    float s[9];
#pragma unroll
    for (int j = 0; j < 9; j++) {
        float lo, hi;
        unpack2(acc[j], lo, hi);
        s[j] = lo + hi;
    }
    float m0 = s[0] + bmu[0], m1 = s[1] + bmu[1], m2 = s[2] + bmu[2];
    float sd0 = sqrtf(softplus_stable(s[3] + bd[0]));
    float sd1 = sqrtf(softplus_stable(s[4] + bd[1]));
    float sd2 = sqrtf(softplus_stable(s[5] + bd[2]));
    float l0 = s[6] + bl[0], l1 = s[7] + bl[1], l2 = s[8] + bl[2];

    float Rm[9];
    rodrigues(m0, m1, m2, Rm);

    for (int jn = 0; jn < n; jn++) {
        size_t base = (size_t)(jn * B + row) * 3;
        float e0 = eps[base + 0], e1 = eps[base + 1], e2 = eps[base + 2];
        float a0 = sd0 * e0, a1 = sd1 * e1, a2 = sd2 * e2;
        float v0 = a0;
        float v1 = l0 * a0 + a1;
        float v2 = l1 * a0 + l2 * a1 + a2;

        float Rv[9];
        rodrigues(v0, v1, v2, Rv);

        float* o = out + (size_t)(jn * B + row) * 9;
#pragma unroll
        for (int i = 0; i < 3; i++) {
#pragma unroll
            for (int k = 0; k < 3; k++) {
                o[i * 3 + k] = Rm[i * 3 + 0] * Rv[0 * 3 + k]
                             + Rm[i * 3 + 1] * Rv[1 * 3 + k]
                             + Rm[i * 3 + 2] * Rv[2 * 3 + k];
            }
        }
    }
}

__global__ void __launch_bounds__(THREADS)
so3_kernel(const float* __restrict__ x, const float* __restrict__ eps,
           const float* __restrict__ Wmu, const float* __restrict__ bmu,
           const float* __restrict__ Wd,  const float* __restrict__ bd,
           const float* __restrict__ Wl,  const float* __restrict__ bl,
           float* __restrict__ out, int B, int n)
{
    extern __shared__ unsigned char smem_raw[];
    u64*   wpkT = (u64*)smem_raw;                         // [j][k2], 9*512 pairs
    float* xs   = (float*)(smem_raw + 9 * NPAIR * 8);     // [STAGES][4 warps][WROWS*ROWPAD]

    const int tid  = threadIdx.x;
    const int w    = tid >> 5;
    const int lane = tid & 31;
    const int row0 = blockIdx.x * TILE_R;

    // This thread's two rows (warp w owns global rows row0+w*32+{0..31, 128..159}).
    const int ra = row0 + w * 32 + lane;
    const int rb = ra + 128;

    // Staging mapping within warp: seg = lane + 32*i (i=0..7); 4 lanes per row.
    const int a  = lane >> 2;            // row within 8-row group
    const int cf = lane & 3;             // 16B quarter of the row's 64B chunk
    // smem byte offsets (within a stage) of this lane's staging targets:
    const unsigned sA = (unsigned)(w * WARP_FLOATS * 4 + (a * ROWPAD + cf * 4) * 4);
    const unsigned sB = sA + 32u * ROWPAD * 4u;
    // global source rows (clamped for safety at the tail):
    int grA = row0 + w * 32 + a;       if (grA > B - 1) grA = B - 1;
    int grB = grA + 128;               if (grB > B - 1) grB = B - 1;
    const float* gA = x + (size_t)grA * D_IN + cf * 4;
    const float* gB = x + (size_t)grB * D_IN + cf * 4;

    const unsigned xs_base = (unsigned)__cvta_generic_to_shared(xs);

    // Issue prologue stages first so loads fly during weight staging.
#pragma unroll
    for (int s = 0; s < STAGES - 1; s++) {
        unsigned base = xs_base + (unsigned)(s * XS_FLOATS * 4);
        const float* pA = gA + s * KC;
        const float* pB = gB + s * KC;
#pragma unroll
        for (int i = 0; i < 4; i++) {
            cp_async16(base + sA + (unsigned)(i * 8 * ROWPAD * 4), pA + (size_t)(8 * i) * D_IN);
            cp_async16(base + sB + (unsigned)(i * 8 * ROWPAD * 4), pB + (size_t)(8 * i) * D_IN);
        }
        cp_commit();
    }

    // Stage weights transposed: wpkT[j*NPAIR + k2] = (W[2k2][c], W[2k2+1][c]).
    for (int i = tid; i < 9 * NPAIR; i += THREADS) {
        int j = i / NPAIR, k2 = i - j * NPAIR;
        const float* W;
        int c;
        if (j < 3)      { W = Wmu; c = j; }
        else if (j < 6) { W = Wd;  c = j - 3; }
        else            { W = Wl;  c = j - 6; }
        wpkT[i] = pack2(W[(2 * k2) * 3 + c], W[(2 * k2 + 1) * 3 + c]);
    }
    __syncthreads();   // weights visible to all warps; mainloop is barrier-free

    u64 accA[9], accB[9];
#pragma unroll
    for (int j = 0; j < 9; j++) { accA[j] = 0ull; accB[j] = 0ull; }

    int slot  = 0;                // slot holding chunk ch (per-warp state)
    int pslot = STAGES - 1;       // slot to prefetch into

#pragma unroll 1
    for (int ch = 0; ch < NCHUNK; ch++) {
        cp_wait1();               // this warp's chunk ch landed
        __syncwarp();             // cross-lane visibility of cp.async data

        if (ch + STAGES - 1 < NCHUNK) {
            unsigned base = xs_base + (unsigned)(pslot * XS_FLOATS * 4);
            const float* pA = gA + (ch + STAGES - 1) * KC;
            const float* pB = gB + (ch + STAGES - 1) * KC;
#pragma unroll
            for (int i = 0; i < 4; i++) {
                cp_async16(base + sA + (unsigned)(i * 8 * ROWPAD * 4), pA + (size_t)(8 * i) * D_IN);
                cp_async16(base + sB + (unsigned)(i * 8 * ROWPAD * 4), pB + (size_t)(8 * i) * D_IN);
            }
            cp_commit();
        }

        // Compute chunk ch for both rows from this warp's partition.
        const float* xra = xs + slot * XS_FLOATS + w * WARP_FLOATS + lane * ROWPAD;
        const float* xrb = xra + 32 * ROWPAD;
        const u64*   wch = wpkT + ch * (KC / 2);
#pragma unroll
        for (int p = 0; p < KC / 4; p++) {                 // 4 quads
            ulonglong2 xav = *(const ulonglong2*)&xra[p * 4];
            ulonglong2 xbv = *(const ulonglong2*)&xrb[p * 4];
#pragma unroll
            for (int j = 0; j < 9; j++) {
                ulonglong2 wv = *(const ulonglong2*)&wch[j * NPAIR + 2 * p];  // broadcast
                ffma2(accA[j], xav.x, wv.x);
                ffma2(accB[j], xbv.x, wv.x);
                ffma2(accA[j], xav.y, wv.y);
                ffma2(accB[j], xbv.y, wv.y);
            }
        }

        slot  = (slot  + 1 == STAGES) ? 0 : slot  + 1;
        pslot = (pslot + 1 == STAGES) ? 0 : pslot + 1;
    }

    if (ra < B) epilogue_row(ra, B, n, accA, bmu, bd, bl, eps, out);
    if (rb < B) epilogue_row(rb, B, n, accB, bmu, bd, bl, eps, out);
}

extern "C" void kernel_launch(void* const* d_in, const int* in_sizes, int n_in,
                              void* d_out, int out_size)
{
    const float* x   = (const float*)d_in[0];
    const float* eps = (const float*)d_in[1];
    const float* Wmu = (const float*)d_in[2];
    const float* bmu = (const float*)d_in[3];
    const float* Wd  = (const float*)d_in[4];
    const float* bd  = (const float*)d_in[5];
    const float* Wl  = (const float*)d_in[6];
    const float* bl  = (const float*)d_in[7];

    const int B = in_sizes[0] / D_IN;
    const int n = in_sizes[1] / (B * 3);

    cudaFuncSetAttribute(so3_kernel, cudaFuncAttributeMaxDynamicSharedMemorySize, SMEM_BYTES);

    const int grid = (B + TILE_R - 1) / TILE_R;
    so3_kernel<<<grid, THREADS, SMEM_BYTES>>>(x, eps, Wmu, bmu, Wd, bd, Wl, bl,
                                              (float*)d_out, B, n);
}